// round 15
// baseline (speedup 1.0000x reference)
#include <cuda_runtime.h>
#include <math.h>
#include <stdint.h>

#define NT   65536
#define NG   32
#define NPG  2048
#define NE   524288
#define HID  128
#define NALIVE1 32768

typedef unsigned long long ull;

// ---------------- scratch (device globals; zero-initialized at load) ---------
__device__ float g_bufA[(size_t)NT * HID];
__device__ float g_bufB[(size_t)NT * HID];
__device__ float g_bufC[(size_t)NT * HID];
__device__ float g_agg [(size_t)NT * HID];
__device__ int   g_cnt[NT];
__device__ int   g_cursor[NT];
__device__ int   g_rowptr[NT + 1];
__device__ int   g_col[NE];
__device__ float g_prel[NT];
__device__ float g_base[NT];
__device__ float g_score[NT];
__device__ float g_nm1[NT];
__device__ float g_ts1[NT];
__device__ float g_gvec[NG * HID];
__device__ int   g_L1[NALIVE1];

// ---------------- helpers ------------------------------------------------------
__device__ __forceinline__ ull ffma2(ull a, ull b, ull c) {
    ull d;
    asm("fma.rn.f32x2 %0, %1, %2, %3;" : "=l"(d) : "l"(a), "l"(b), "l"(c));
    return d;
}
__device__ __forceinline__ ull dup_lo(ull v) {
    ull r;
    asm("{\n\t.reg .b32 l, h;\n\tmov.b64 {l, h}, %1;\n\tmov.b64 %0, {l, l};\n\t}"
        : "=l"(r) : "l"(v));
    return r;
}
__device__ __forceinline__ ull dup_hi(ull v) {
    ull r;
    asm("{\n\t.reg .b32 l, h;\n\tmov.b64 {l, h}, %1;\n\tmov.b64 %0, {h, h};\n\t}"
        : "=l"(r) : "l"(v));
    return r;
}
__device__ __forceinline__ void unpack2(ull v, float& lo, float& hi) {
    asm("mov.b64 {%0, %1}, %2;" : "=f"(lo), "=f"(hi) : "l"(v));
}
__device__ __forceinline__ uint32_t s2u(const void* p) {
    return (uint32_t)__cvta_generic_to_shared(p);
}
__device__ __forceinline__ void cp16(uint32_t saddr, const void* gaddr) {
    asm volatile("cp.async.cg.shared.global [%0], [%1], 16;"
                 :: "r"(saddr), "l"(gaddr));
}
__device__ __forceinline__ void cp_commit() {
    asm volatile("cp.async.commit_group;" ::: "memory");
}
template<int N> __device__ __forceinline__ void cp_wait() {
    asm volatile("cp.async.wait_group %0;" :: "n"(N) : "memory");
}

// ---------------- CSR build ----------------------------------------------------
__global__ void k_hist(const int* __restrict__ dst) {
    int e = blockIdx.x * blockDim.x + threadIdx.x;
    if (e < NE) atomicAdd(&g_cnt[dst[e]], 1);   // restored to 0 by k_score_agg
}

__global__ void k_scan() {
    __shared__ int sums[1024];
    int t = threadIdx.x;
    int base = t * 64;
    int s = 0;
    #pragma unroll 8
    for (int i = 0; i < 64; i++) s += g_cnt[base + i];
    sums[t] = s;
    __syncthreads();
    for (int off = 1; off < 1024; off <<= 1) {
        int v = (t >= off) ? sums[t - off] : 0;
        __syncthreads();
        sums[t] += v;
        __syncthreads();
    }
    int run = (t == 0) ? 0 : sums[t - 1];
    for (int i = 0; i < 64; i++) { g_rowptr[base + i] = run; run += g_cnt[base + i]; }
    if (t == 1023) g_rowptr[NT] = run;
}

__global__ void k_scatter(const int* __restrict__ src, const int* __restrict__ dst) {
    int e = blockIdx.x * blockDim.x + threadIdx.x;
    if (e >= NE) return;
    int d = dst[e];
    int pos = g_rowptr[d] + atomicAdd(&g_cursor[d], 1);  // restored later
    g_col[pos] = src[e];
}

// ---------------- GEMM: 128x128 tile, 3-stage cp.async pipeline, f32x2 --------
// out = relu( A1@W1 + A2@W2 + bias ), K = 128+128 in 8 phases of 32.
// As row-major [row][k] (cp.async direct), Bs natural [k][col].
// Thread tile: 8 rows x 8 cols (4 col-pair f32x2 accumulators).
// SCORES: also emits g_prel/g_base from the post-relu rows (pool score GEMVs).
__device__ __forceinline__ void stage_phase(
    const float* __restrict__ Ap, const float* __restrict__ Wp, int kk,
    const int* __restrict__ Lmap, int r0, bool gather,
    float* Asb, float* Bsb, int tid)
{
    #pragma unroll
    for (int i = 0; i < 4; i++) {
        int c = tid + i * 256;          // 128 rows x 8 16B-chunks
        int row = c >> 3, q = c & 7;
        int grow = gather ? __ldg(&Lmap[r0 + row]) : (r0 + row);
        cp16(s2u(Asb + row * 32 + q * 4),
             Ap + (size_t)grow * 128 + kk + q * 4);
    }
    #pragma unroll
    for (int i = 0; i < 4; i++) {
        int c = tid + i * 256;          // 32 k x 32 16B-chunks
        int k = c >> 5, q = c & 31;
        cp16(s2u(Bsb + k * 128 + q * 4),
             Wp + (size_t)(kk + k) * 128 + q * 4);
    }
}

template<bool IDXA2, bool SCORES>
__global__ __launch_bounds__(256, 2) void k_gemm(
    const float* __restrict__ A1, const float* __restrict__ W1,
    const float* __restrict__ A2, const float* __restrict__ W2,
    const float* __restrict__ bias, const int* __restrict__ Lmap,
    const float* __restrict__ Prel, const float* __restrict__ Proot,
    const float* __restrict__ prb, float* __restrict__ out)
{
    extern __shared__ float sm[];
    float* As = sm;               // 3 x 128 x 32
    float* Bs = sm + 12288;       // 3 x 32 x 128
    const int NPH = 8;
    int tid = threadIdx.x;
    int r0 = blockIdx.x * 128;
    int ty = tid >> 4, tx = tid & 15;   // rows ty*8+i, col-pairs tx+16j

    ull acc[8][4];
    #pragma unroll
    for (int i = 0; i < 8; i++)
        #pragma unroll
        for (int j = 0; j < 4; j++) acc[i][j] = 0ULL;

    // prologue: stage phases 0 and 1
    stage_phase(A1, W1, 0, Lmap, r0, false, As, Bs, tid);
    cp_commit();
    stage_phase(A1, W1, 32, Lmap, r0, false, As + 4096, Bs + 4096, tid);
    cp_commit();

    for (int p = 0; p < NPH; p++) {
        int buf = p % 3;
        // prefetch phase p+2 into buffer (p+2)%3 (last read at phase p-1)
        if (p + 2 < NPH) {
            int pn = p + 2;
            bool second = (pn >= 4);
            const float* Ap = second ? A2 : A1;
            const float* Wp = second ? W2 : W1;
            bool g = IDXA2 && second;
            int bn = pn % 3;
            stage_phase(Ap, Wp, (pn & 3) * 32, Lmap, r0, g,
                        As + bn * 4096, Bs + bn * 4096, tid);
            cp_commit();
            cp_wait<2>();           // phase p's group complete
        } else if (p + 1 < NPH) {
            cp_wait<1>();
        } else {
            cp_wait<0>();
        }
        __syncthreads();            // all threads' copies for phase p visible

        const float* Ab = As + buf * 4096 + (ty * 8) * 32;
        const float* Bb = Bs + buf * 4096;
        #pragma unroll 4
        for (int k2 = 0; k2 < 16; k2++) {
            ull ap[8];
            #pragma unroll
            for (int i = 0; i < 8; i++)
                ap[i] = *(const ull*)(Ab + i * 32 + 2 * k2);
            #pragma unroll
            for (int h = 0; h < 2; h++) {
                ull a[8];
                #pragma unroll
                for (int i = 0; i < 8; i++)
                    a[i] = h ? dup_hi(ap[i]) : dup_lo(ap[i]);
                const float* Bk = Bb + (2 * k2 + h) * 128;
                #pragma unroll
                for (int j = 0; j < 4; j++) {
                    ull b = *(const ull*)(Bk + 2 * (tx + 16 * j));
                    #pragma unroll
                    for (int i = 0; i < 8; i++)
                        acc[i][j] = ffma2(a[i], b, acc[i][j]);
                }
            }
        }
        __syncthreads();            // done reading buf before it is restaged
    }

    // epilogue: bias + relu (+ scatter) (+ pool score GEMVs)
    float prb0 = SCORES ? __ldg(&prb[0]) : 0.f;
    #pragma unroll
    for (int i = 0; i < 8; i++) {
        int rl = ty * 8 + i;
        int gr = IDXA2 ? __ldg(&Lmap[r0 + rl]) : (r0 + rl);
        float s1 = 0.f, s2 = 0.f;
        #pragma unroll
        for (int j = 0; j < 4; j++) {
            int cc = 2 * (tx + 16 * j);
            float lo, hi;
            unpack2(acc[i][j], lo, hi);
            lo = fmaxf(lo + bias[cc], 0.f);
            hi = fmaxf(hi + bias[cc + 1], 0.f);
            if (SCORES) {
                s1 += lo * __ldg(&Prel[cc])  + hi * __ldg(&Prel[cc + 1]);
                s2 += lo * __ldg(&Proot[cc]) + hi * __ldg(&Proot[cc + 1]);
            }
            *(float2*)(out + (size_t)gr * 128 + cc) = make_float2(lo, hi);
        }
        if (SCORES) {
            #pragma unroll
            for (int off = 8; off > 0; off >>= 1) {
                s1 += __shfl_xor_sync(0xffffffffu, s1, off, 16);
                s2 += __shfl_xor_sync(0xffffffffu, s2, off, 16);
            }
            if ((tid & 15) == 0) {
                g_prel[gr] = s1;
                g_base[gr] = s2 + prb0;
            }
        }
    }
}

// ---------------- mean aggregation (warp per work item, 8-way MLP) ------------
__global__ void k_agg(const float* __restrict__ h, float* __restrict__ out,
                      const float* __restrict__ wts, const float* __restrict__ nm,
                      const int* __restrict__ L, int nwork) {
    int w    = (blockIdx.x * blockDim.x + threadIdx.x) >> 5;
    int lane = threadIdx.x & 31;
    if (w >= nwork) return;
    int n = L ? __ldg(&L[w]) : w;
    int r0 = g_rowptr[n], r1 = g_rowptr[n + 1];
    float4 acc = make_float4(0.f, 0.f, 0.f, 0.f);
    float cnt = 0.f;
    int j = r0;
    for (; j + 8 <= r1; j += 8) {
        int cI[8];
        #pragma unroll
        for (int q = 0; q < 8; q++) cI[q] = g_col[j + q];
        float wv[8];
        #pragma unroll
        for (int q = 0; q < 8; q++) wv[q] = wts ? wts[cI[q]] : 1.f;
        float4 v[8];
        #pragma unroll
        for (int q = 0; q < 8; q++)
            v[q] = *(const float4*)(h + (size_t)cI[q] * HID + lane * 4);
        #pragma unroll
        for (int q = 0; q < 8; q++) {
            acc.x += v[q].x * wv[q];
            acc.y += v[q].y * wv[q];
            acc.z += v[q].z * wv[q];
            acc.w += v[q].w * wv[q];
        }
        if (nm) {
            #pragma unroll
            for (int q = 0; q < 8; q++) cnt += nm[cI[q]];
        }
    }
    for (; j < r1; j++) {
        int c = g_col[j];
        float ww = wts ? wts[c] : 1.f;
        float4 v = *(const float4*)(h + (size_t)c * HID + lane * 4);
        acc.x += v.x*ww; acc.y += v.y*ww; acc.z += v.z*ww; acc.w += v.w*ww;
        if (nm) cnt += nm[c];
    }
    float inv = nm ? (1.f / fmaxf(cnt, 1.f))
                   : (1.f / fmaxf((float)(r1 - r0), 1.f));
    acc.x *= inv; acc.y *= inv; acc.z *= inv; acc.w *= inv;
    *(float4*)(out + (size_t)w * HID + lane * 4) = acc;
}

// ---------------- pooling ------------------------------------------------------
// score[n] = base[n] + sum_in prel[src]*nm[src]; also restores CSR scratch.
__global__ void k_score_agg(const float* __restrict__ nm) {
    int n = blockIdx.x * blockDim.x + threadIdx.x;
    if (n >= NT) return;
    g_cnt[n] = 0; g_cursor[n] = 0;     // restore for next replay (idempotent)
    if (nm && nm[n] == 0.f) { g_score[n] = -1e30f; return; }
    float s = g_base[n];
    int r0 = g_rowptr[n], r1 = g_rowptr[n + 1];
    int j = r0;
    for (; j + 4 <= r1; j += 4) {
        int c0 = g_col[j], c1 = g_col[j+1], c2 = g_col[j+2], c3 = g_col[j+3];
        float p0 = g_prel[c0] * (nm ? nm[c0] : 1.f);
        float p1 = g_prel[c1] * (nm ? nm[c1] : 1.f);
        float p2 = g_prel[c2] * (nm ? nm[c2] : 1.f);
        float p3 = g_prel[c3] * (nm ? nm[c3] : 1.f);
        s += p0 + p1 + p2 + p3;
    }
    for (; j < r1; j++) {
        int c = g_col[j];
        s += g_prel[c] * (nm ? nm[c] : 1.f);
    }
    g_score[n] = s;
}

// exact top-k per graph via bitonic sort.
// mode 1 (pool-1, k=1024): writes full 0/1 mask to nm_out, ts1 = tanh(score)
//   for kept / 0 for dead, alive list at g_L1[g*k ..].
// mode 2 (pool-2, k=512): nm_out unused (nullptr); ts1 + alive list for kept
//   only; zeroes g_gvec.
__global__ __launch_bounds__(1024) void k_topk(float* __restrict__ nm_out,
                                               int k, int mode) {
    __shared__ ull keys[NPG];
    int g = blockIdx.x, t = threadIdx.x;
    if (mode == 2 && t < 128) g_gvec[g * 128 + t] = 0.f;
    for (int i = t; i < NPG; i += 1024) {
        float f = g_score[g * NPG + i];
        unsigned u = __float_as_uint(f);
        u = (u & 0x80000000u) ? ~u : (u | 0x80000000u);   // order-preserving map
        keys[i] = (((ull)u) << 32) | (unsigned)(0xFFFFFFFFu - i);
    }
    __syncthreads();
    for (int ksz = 2; ksz <= NPG; ksz <<= 1) {
        for (int j = ksz >> 1; j > 0; j >>= 1) {
            int i   = ((t & ~(j - 1)) << 1) | (t & (j - 1));
            int ixj = i | j;
            bool asc = ((i & ksz) == 0);
            ull a = keys[i], b = keys[ixj];
            if ((a > b) == asc) { keys[i] = b; keys[ixj] = a; }
            __syncthreads();
        }
    }
    for (int i = t; i < NPG; i += 1024) {
        ull key = keys[i];
        unsigned kh = (unsigned)(key >> 32);
        int idx = (int)(0xFFFFFFFFu - (unsigned)(key & 0xFFFFFFFFu));
        bool keep = (i >= NPG - k);
        int node = g * NPG + idx;
        if (nm_out) nm_out[node] = keep ? 1.f : 0.f;
        unsigned ou = (kh & 0x80000000u) ? (kh & 0x7FFFFFFFu) : ~kh;
        if (keep) {
            g_ts1[node] = tanhf(__uint_as_float(ou));
            g_L1[g * k + (i - (NPG - k))] = node;
        } else if (mode == 1) {
            g_ts1[node] = 0.f;
        }
    }
}

// bufC[alive rows] = bufB * ts1 (only alive rows are ever read downstream)
__global__ void k_hupdate_alive(const float* __restrict__ hin,
                                float* __restrict__ hout) {
    int w    = (blockIdx.x * blockDim.x + threadIdx.x) >> 5;
    int lane = threadIdx.x & 31;
    if (w >= NALIVE1) return;
    int n = g_L1[w];
    float tsv = g_ts1[n];
    float4 v = *(const float4*)(hin + (size_t)n * HID + lane * 4);
    v.x *= tsv; v.y *= tsv; v.z *= tsv; v.w *= tsv;
    *(float4*)(hout + (size_t)n * HID + lane * 4) = v;
}

// ---------------- readout: gather only the 512 survivors per graph ------------
__global__ void k_graph_reduce(const float* __restrict__ h) {
    __shared__ float ts[128];
    __shared__ int   nd[128];
    int g = blockIdx.x >> 2, chunk = blockIdx.x & 3;
    int c = threadIdx.x;
    int slot = g * 512 + chunk * 128 + c;
    int node = g_L1[slot];
    nd[c] = node;
    ts[c] = g_ts1[node];
    __syncthreads();
    float s = 0.f;
    #pragma unroll 8
    for (int n = 0; n < 128; n++)
        s += h[(size_t)nd[n] * HID + c] * ts[n];
    atomicAdd(&g_gvec[g * HID + c], s * (1.f / 512.f));
}

__global__ __launch_bounds__(1024) void k_head(
    const float* __restrict__ W5, const float* __restrict__ b5,
    const float* __restrict__ W6, const float* __restrict__ b6,
    float* __restrict__ out)
{
    __shared__ float hid[NG][64];
    int w = threadIdx.x >> 5, lane = threadIdx.x & 31;
    for (int c = lane; c < 64; c += 32) {
        float s = b5[c];
        #pragma unroll 8
        for (int i = 0; i < HID; i++) s += g_gvec[w * HID + i] * W5[i * 64 + c];
        hid[w][c] = fmaxf(s, 0.f);
    }
    __syncwarp();
    if (lane == 0) {
        float l0 = b6[0], l1 = b6[1];
        #pragma unroll 8
        for (int i = 0; i < 64; i++) {
            float hv = hid[w][i];
            l0 += hv * W6[i * 2 + 0];
            l1 += hv * W6[i * 2 + 1];
        }
        float m = fmaxf(l0, l1);
        float lse = m + logf(expf(l0 - m) + expf(l1 - m));
        out[w * 2 + 0] = l0 - lse;
        out[w * 2 + 1] = l1 - lse;
    }
}

// ---------------- launch ---------------------------------------------------------
extern "C" void kernel_launch(void* const* d_in, const int* in_sizes, int n_in,
                              void* d_out, int out_size) {
    (void)in_sizes; (void)n_in; (void)out_size;
    const float* x   = (const float*)d_in[0];
    const int*   ei  = (const int*)d_in[1];
    const int*   src = ei;
    const int*   dst = ei + NE;
    const float* Wl1 = (const float*)d_in[4],  *bl1 = (const float*)d_in[5],  *Wr1 = (const float*)d_in[6];
    const float* Wl2 = (const float*)d_in[7],  *bl2 = (const float*)d_in[8],  *Wr2 = (const float*)d_in[9];
    const float* Wl3 = (const float*)d_in[10], *bl3 = (const float*)d_in[11], *Wr3 = (const float*)d_in[12];
    const float* Wl4 = (const float*)d_in[13], *bl4 = (const float*)d_in[14], *Wr4 = (const float*)d_in[15];
    const float* Prel1 = (const float*)d_in[16], *prb1 = (const float*)d_in[17], *Proot1 = (const float*)d_in[18];
    const float* Prel2 = (const float*)d_in[19], *prb2 = (const float*)d_in[20], *Proot2 = (const float*)d_in[21];
    const float* W5 = (const float*)d_in[22], *b5 = (const float*)d_in[23];
    const float* W6 = (const float*)d_in[24], *b6 = (const float*)d_in[25];
    float* out = (float*)d_out;

    float *bufA, *bufB, *bufC, *agg, *nm1, *ts1;
    int *L1;
    cudaGetSymbolAddress((void**)&bufA, g_bufA);
    cudaGetSymbolAddress((void**)&bufB, g_bufB);
    cudaGetSymbolAddress((void**)&bufC, g_bufC);
    cudaGetSymbolAddress((void**)&agg,  g_agg);
    cudaGetSymbolAddress((void**)&nm1,  g_nm1);
    cudaGetSymbolAddress((void**)&ts1,  g_ts1);
    cudaGetSymbolAddress((void**)&L1,   g_L1);

    const int SMEM = 98304;   // 3 stages x (16KB A + 16KB B)
    cudaFuncSetAttribute(k_gemm<false,false>,
                         cudaFuncAttributeMaxDynamicSharedMemorySize, SMEM);
    cudaFuncSetAttribute(k_gemm<false,true>,
                         cudaFuncAttributeMaxDynamicSharedMemorySize, SMEM);
    cudaFuncSetAttribute(k_gemm<true,false>,
                         cudaFuncAttributeMaxDynamicSharedMemorySize, SMEM);
    cudaFuncSetAttribute(k_gemm<true,true>,
                         cudaFuncAttributeMaxDynamicSharedMemorySize, SMEM);

    const int AGG_FULL    = (NT * 32) / 256;
    const int AGG_COMPACT = (NALIVE1 * 32) / 256;
    const int GEMM_FULL    = NT / 128;       // 512 blocks
    const int GEMM_COMPACT = NALIVE1 / 128;  // 256 blocks

    // 1-3: CSR build (g_cnt/g_cursor zero at entry; restored by k_score_agg)
    k_hist<<<NE / 256, 256>>>(dst);
    k_scan<<<1, 1024>>>();
    k_scatter<<<NE / 256, 256>>>(src, dst);

    // 4: agg(x)
    k_agg<<<AGG_FULL, 256>>>(x, agg, nullptr, nullptr, nullptr, NT);
    // 5: SAGE 1: bufA = relu(agg@Wl1 + x@Wr1 + bl1)
    k_gemm<false,false><<<GEMM_FULL, 256, SMEM>>>(
        agg, Wl1, x, Wr1, bl1, nullptr, nullptr, nullptr, nullptr, bufA);
    // 6-7: SAGE 2 (+ pool-1 score GEMVs in epilogue)
    k_agg<<<AGG_FULL, 256>>>(bufA, agg, nullptr, nullptr, nullptr, NT);
    k_gemm<false,true><<<GEMM_FULL, 256, SMEM>>>(
        agg, Wl2, bufA, Wr2, bl2, nullptr, Prel1, Proot1, prb1, bufB);

    // 8-9: SAGPool 1 (k=1024): score scatter, sort -> nm1 + ts1 + alive list L1
    k_score_agg<<<NT / 256, 256>>>(nullptr);
    k_topk<<<NG, 1024>>>(nm1, 1024, 1);
    // 10: bufC[alive] = bufB * ts1
    k_hupdate_alive<<<AGG_COMPACT, 256>>>(bufB, bufC);

    // 11-12: SAGE 3 on compacted rows (agg reads bufB with feature weight ts1)
    k_agg<<<AGG_COMPACT, 256>>>(bufB, agg, ts1, nm1, L1, NALIVE1);
    k_gemm<true,false><<<GEMM_COMPACT, 256, SMEM>>>(
        agg, Wl3, bufC, Wr3, bl3, L1, nullptr, nullptr, nullptr, bufA);
    // 13-14: SAGE 4 (+ pool-2 score GEMVs in epilogue, alive rows only)
    k_agg<<<AGG_COMPACT, 256>>>(bufA, agg, nm1, nm1, L1, NALIVE1);
    k_gemm<true,true><<<GEMM_COMPACT, 256, SMEM>>>(
        agg, Wl4, bufA, Wr4, bl4, L1, Prel2, Proot2, prb2, bufB);

    // 15-16: SAGPool 2 (k=512): emits ts1 + alive list (stride 512), zeroes gvec
    k_score_agg<<<NT / 256, 256>>>(nm1);
    k_topk<<<NG, 1024>>>(nullptr, 512, 2);

    // 17-18: readout over survivors only
    k_graph_reduce<<<128, 128>>>(bufB);
    k_head<<<1, 1024>>>(W5, b5, W6, b6, out);
}

// round 16
// speedup vs baseline: 1.0166x; 1.0166x over previous
#include <cuda_runtime.h>
#include <math.h>
#include <stdint.h>

#define NT   65536
#define NG   32
#define NPG  2048
#define NE   524288
#define HID  128
#define NALIVE1 32768

typedef unsigned long long ull;

// ---------------- scratch (device globals; zero-initialized at load) ---------
__device__ float g_bufA[(size_t)NT * HID];
__device__ float g_bufB[(size_t)NT * HID];
__device__ float g_bufC[(size_t)NT * HID];
__device__ float g_agg [(size_t)NT * HID];
__device__ int   g_cnt[NT];
__device__ int   g_cursor[NT];
__device__ int   g_rowptr[NT + 1];
__device__ int   g_col[NE];
__device__ float g_prel[NT];
__device__ float g_base[NT];
__device__ float g_score[NT];
__device__ float g_nm1[NT];
__device__ float g_ts1[NT];
__device__ float g_gvec[NG * HID];
__device__ int   g_L1[NALIVE1];

// ---------------- helpers ------------------------------------------------------
__device__ __forceinline__ ull ffma2(ull a, ull b, ull c) {
    ull d;
    asm("fma.rn.f32x2 %0, %1, %2, %3;" : "=l"(d) : "l"(a), "l"(b), "l"(c));
    return d;
}
__device__ __forceinline__ ull dup_lo(ull v) {
    ull r;
    asm("{\n\t.reg .b32 l, h;\n\tmov.b64 {l, h}, %1;\n\tmov.b64 %0, {l, l};\n\t}"
        : "=l"(r) : "l"(v));
    return r;
}
__device__ __forceinline__ ull dup_hi(ull v) {
    ull r;
    asm("{\n\t.reg .b32 l, h;\n\tmov.b64 {l, h}, %1;\n\tmov.b64 %0, {h, h};\n\t}"
        : "=l"(r) : "l"(v));
    return r;
}
__device__ __forceinline__ void unpack2(ull v, float& lo, float& hi) {
    asm("mov.b64 {%0, %1}, %2;" : "=f"(lo), "=f"(hi) : "l"(v));
}
__device__ __forceinline__ uint32_t s2u(const void* p) {
    return (uint32_t)__cvta_generic_to_shared(p);
}
__device__ __forceinline__ void cp16(uint32_t saddr, const void* gaddr) {
    asm volatile("cp.async.cg.shared.global [%0], [%1], 16;"
                 :: "r"(saddr), "l"(gaddr));
}
__device__ __forceinline__ void cp_commit() {
    asm volatile("cp.async.commit_group;" ::: "memory");
}
template<int N> __device__ __forceinline__ void cp_wait() {
    asm volatile("cp.async.wait_group %0;" :: "n"(N) : "memory");
}

// ---------------- CSR build ----------------------------------------------------
__global__ void k_hist(const int* __restrict__ dst) {
    int e = blockIdx.x * blockDim.x + threadIdx.x;
    if (e < NE) atomicAdd(&g_cnt[dst[e]], 1);   // restored to 0 by k_score_agg
}

__global__ void k_scan() {
    __shared__ int sums[1024];
    int t = threadIdx.x;
    int base = t * 64;
    int s = 0;
    #pragma unroll 8
    for (int i = 0; i < 64; i++) s += g_cnt[base + i];
    sums[t] = s;
    __syncthreads();
    for (int off = 1; off < 1024; off <<= 1) {
        int v = (t >= off) ? sums[t - off] : 0;
        __syncthreads();
        sums[t] += v;
        __syncthreads();
    }
    int run = (t == 0) ? 0 : sums[t - 1];
    for (int i = 0; i < 64; i++) { g_rowptr[base + i] = run; run += g_cnt[base + i]; }
    if (t == 1023) g_rowptr[NT] = run;
}

__global__ void k_scatter(const int* __restrict__ src, const int* __restrict__ dst) {
    int e = blockIdx.x * blockDim.x + threadIdx.x;
    if (e >= NE) return;
    int d = dst[e];
    int pos = g_rowptr[d] + atomicAdd(&g_cursor[d], 1);  // restored later
    g_col[pos] = src[e];
}

// ---------------- GEMM: 128x128 tile, 3-stage cp.async pipeline, f32x2 --------
// out = relu( A1@W1 + A2@W2 + bias ), K = 128+128 in 8 phases of 32.
// As row-major [row][k] (cp.async direct), Bs natural [k][col].
// Thread tile: 8 rows x 8 cols (4 col-pair f32x2 accumulators).
// SCORES: also emits g_prel/g_base from the post-relu rows (pool score GEMVs).
__device__ __forceinline__ void stage_phase(
    const float* __restrict__ Ap, const float* __restrict__ Wp, int kk,
    const int* __restrict__ Lmap, int r0, bool gather,
    float* Asb, float* Bsb, int tid)
{
    #pragma unroll
    for (int i = 0; i < 4; i++) {
        int c = tid + i * 256;          // 128 rows x 8 16B-chunks
        int row = c >> 3, q = c & 7;
        int grow = gather ? __ldg(&Lmap[r0 + row]) : (r0 + row);
        cp16(s2u(Asb + row * 32 + q * 4),
             Ap + (size_t)grow * 128 + kk + q * 4);
    }
    #pragma unroll
    for (int i = 0; i < 4; i++) {
        int c = tid + i * 256;          // 32 k x 32 16B-chunks
        int k = c >> 5, q = c & 31;
        cp16(s2u(Bsb + k * 128 + q * 4),
             Wp + (size_t)(kk + k) * 128 + q * 4);
    }
}

template<bool IDXA2, bool SCORES>
__global__ __launch_bounds__(256, 2) void k_gemm(
    const float* __restrict__ A1, const float* __restrict__ W1,
    const float* __restrict__ A2, const float* __restrict__ W2,
    const float* __restrict__ bias, const int* __restrict__ Lmap,
    const float* __restrict__ Prel, const float* __restrict__ Proot,
    const float* __restrict__ prb, float* __restrict__ out)
{
    extern __shared__ float sm[];
    float* As = sm;               // 3 x 128 x 32
    float* Bs = sm + 12288;       // 3 x 32 x 128
    const int NPH = 8;
    int tid = threadIdx.x;
    int r0 = blockIdx.x * 128;
    int ty = tid >> 4, tx = tid & 15;   // rows ty*8+i, col-pairs tx+16j

    ull acc[8][4];
    #pragma unroll
    for (int i = 0; i < 8; i++)
        #pragma unroll
        for (int j = 0; j < 4; j++) acc[i][j] = 0ULL;

    // prologue: stage phases 0 and 1
    stage_phase(A1, W1, 0, Lmap, r0, false, As, Bs, tid);
    cp_commit();
    stage_phase(A1, W1, 32, Lmap, r0, false, As + 4096, Bs + 4096, tid);
    cp_commit();

    for (int p = 0; p < NPH; p++) {
        int buf = p % 3;
        // prefetch phase p+2 into buffer (p+2)%3 (last read at phase p-1)
        if (p + 2 < NPH) {
            int pn = p + 2;
            bool second = (pn >= 4);
            const float* Ap = second ? A2 : A1;
            const float* Wp = second ? W2 : W1;
            bool g = IDXA2 && second;
            int bn = pn % 3;
            stage_phase(Ap, Wp, (pn & 3) * 32, Lmap, r0, g,
                        As + bn * 4096, Bs + bn * 4096, tid);
            cp_commit();
            cp_wait<2>();           // phase p's group complete
        } else if (p + 1 < NPH) {
            cp_wait<1>();
        } else {
            cp_wait<0>();
        }
        __syncthreads();            // all threads' copies for phase p visible

        const float* Ab = As + buf * 4096 + (ty * 8) * 32;
        const float* Bb = Bs + buf * 4096;
        #pragma unroll 2
        for (int k2 = 0; k2 < 16; k2++) {
            ull ap[8];
            #pragma unroll
            for (int i = 0; i < 8; i++)
                ap[i] = *(const ull*)(Ab + i * 32 + 2 * k2);
            #pragma unroll
            for (int h = 0; h < 2; h++) {
                ull a[8];
                #pragma unroll
                for (int i = 0; i < 8; i++)
                    a[i] = h ? dup_hi(ap[i]) : dup_lo(ap[i]);
                const float* Bk = Bb + (2 * k2 + h) * 128;
                #pragma unroll
                for (int j = 0; j < 4; j++) {
                    ull b = *(const ull*)(Bk + 2 * (tx + 16 * j));
                    #pragma unroll
                    for (int i = 0; i < 8; i++)
                        acc[i][j] = ffma2(a[i], b, acc[i][j]);
                }
            }
        }
        __syncthreads();            // done reading buf before it is restaged
    }

    // epilogue: bias + relu (+ scatter) (+ pool score GEMVs)
    float prb0 = SCORES ? __ldg(&prb[0]) : 0.f;
    #pragma unroll
    for (int i = 0; i < 8; i++) {
        int rl = ty * 8 + i;
        int gr = IDXA2 ? __ldg(&Lmap[r0 + rl]) : (r0 + rl);
        float s1 = 0.f, s2 = 0.f;
        #pragma unroll
        for (int j = 0; j < 4; j++) {
            int cc = 2 * (tx + 16 * j);
            float lo, hi;
            unpack2(acc[i][j], lo, hi);
            lo = fmaxf(lo + bias[cc], 0.f);
            hi = fmaxf(hi + bias[cc + 1], 0.f);
            if (SCORES) {
                s1 += lo * __ldg(&Prel[cc])  + hi * __ldg(&Prel[cc + 1]);
                s2 += lo * __ldg(&Proot[cc]) + hi * __ldg(&Proot[cc + 1]);
            }
            *(float2*)(out + (size_t)gr * 128 + cc) = make_float2(lo, hi);
        }
        if (SCORES) {
            #pragma unroll
            for (int off = 8; off > 0; off >>= 1) {
                s1 += __shfl_xor_sync(0xffffffffu, s1, off, 16);
                s2 += __shfl_xor_sync(0xffffffffu, s2, off, 16);
            }
            if ((tid & 15) == 0) {
                g_prel[gr] = s1;
                g_base[gr] = s2 + prb0;
            }
        }
    }
}

// ---------------- mean aggregation (warp per work item, 8-way MLP) ------------
__global__ void k_agg(const float* __restrict__ h, float* __restrict__ out,
                      const float* __restrict__ wts, const float* __restrict__ nm,
                      const int* __restrict__ L, int nwork) {
    int w    = (blockIdx.x * blockDim.x + threadIdx.x) >> 5;
    int lane = threadIdx.x & 31;
    if (w >= nwork) return;
    int n = L ? __ldg(&L[w]) : w;
    int r0 = g_rowptr[n], r1 = g_rowptr[n + 1];
    float4 acc = make_float4(0.f, 0.f, 0.f, 0.f);
    float cnt = 0.f;
    int j = r0;
    for (; j + 8 <= r1; j += 8) {
        int cI[8];
        #pragma unroll
        for (int q = 0; q < 8; q++) cI[q] = g_col[j + q];
        float wv[8];
        #pragma unroll
        for (int q = 0; q < 8; q++) wv[q] = wts ? wts[cI[q]] : 1.f;
        float4 v[8];
        #pragma unroll
        for (int q = 0; q < 8; q++)
            v[q] = *(const float4*)(h + (size_t)cI[q] * HID + lane * 4);
        #pragma unroll
        for (int q = 0; q < 8; q++) {
            acc.x += v[q].x * wv[q];
            acc.y += v[q].y * wv[q];
            acc.z += v[q].z * wv[q];
            acc.w += v[q].w * wv[q];
        }
        if (nm) {
            #pragma unroll
            for (int q = 0; q < 8; q++) cnt += nm[cI[q]];
        }
    }
    for (; j < r1; j++) {
        int c = g_col[j];
        float ww = wts ? wts[c] : 1.f;
        float4 v = *(const float4*)(h + (size_t)c * HID + lane * 4);
        acc.x += v.x*ww; acc.y += v.y*ww; acc.z += v.z*ww; acc.w += v.w*ww;
        if (nm) cnt += nm[c];
    }
    float inv = nm ? (1.f / fmaxf(cnt, 1.f))
                   : (1.f / fmaxf((float)(r1 - r0), 1.f));
    acc.x *= inv; acc.y *= inv; acc.z *= inv; acc.w *= inv;
    *(float4*)(out + (size_t)w * HID + lane * 4) = acc;
}

// ---------------- pooling ------------------------------------------------------
// score[n] = base[n] + sum_in prel[src]*nm[src]; also restores CSR scratch.
__global__ void k_score_agg(const float* __restrict__ nm) {
    int n = blockIdx.x * blockDim.x + threadIdx.x;
    if (n >= NT) return;
    g_cnt[n] = 0; g_cursor[n] = 0;     // restore for next replay (idempotent)
    if (nm && nm[n] == 0.f) { g_score[n] = -1e30f; return; }
    float s = g_base[n];
    int r0 = g_rowptr[n], r1 = g_rowptr[n + 1];
    int j = r0;
    for (; j + 4 <= r1; j += 4) {
        int c0 = g_col[j], c1 = g_col[j+1], c2 = g_col[j+2], c3 = g_col[j+3];
        float p0 = g_prel[c0] * (nm ? nm[c0] : 1.f);
        float p1 = g_prel[c1] * (nm ? nm[c1] : 1.f);
        float p2 = g_prel[c2] * (nm ? nm[c2] : 1.f);
        float p3 = g_prel[c3] * (nm ? nm[c3] : 1.f);
        s += p0 + p1 + p2 + p3;
    }
    for (; j < r1; j++) {
        int c = g_col[j];
        s += g_prel[c] * (nm ? nm[c] : 1.f);
    }
    g_score[n] = s;
}

// exact top-k per graph via bitonic sort.
// mode 1 (pool-1, k=1024): writes full 0/1 mask to nm_out, ts1 = tanh(score)
//   for kept / 0 for dead, alive list at g_L1[g*k ..].
// mode 2 (pool-2, k=512): nm_out unused (nullptr); ts1 + alive list for kept
//   only; zeroes g_gvec.
__global__ __launch_bounds__(1024) void k_topk(float* __restrict__ nm_out,
                                               int k, int mode) {
    __shared__ ull keys[NPG];
    int g = blockIdx.x, t = threadIdx.x;
    if (mode == 2 && t < 128) g_gvec[g * 128 + t] = 0.f;
    for (int i = t; i < NPG; i += 1024) {
        float f = g_score[g * NPG + i];
        unsigned u = __float_as_uint(f);
        u = (u & 0x80000000u) ? ~u : (u | 0x80000000u);   // order-preserving map
        keys[i] = (((ull)u) << 32) | (unsigned)(0xFFFFFFFFu - i);
    }
    __syncthreads();
    for (int ksz = 2; ksz <= NPG; ksz <<= 1) {
        for (int j = ksz >> 1; j > 0; j >>= 1) {
            int i   = ((t & ~(j - 1)) << 1) | (t & (j - 1));
            int ixj = i | j;
            bool asc = ((i & ksz) == 0);
            ull a = keys[i], b = keys[ixj];
            if ((a > b) == asc) { keys[i] = b; keys[ixj] = a; }
            __syncthreads();
        }
    }
    for (int i = t; i < NPG; i += 1024) {
        ull key = keys[i];
        unsigned kh = (unsigned)(key >> 32);
        int idx = (int)(0xFFFFFFFFu - (unsigned)(key & 0xFFFFFFFFu));
        bool keep = (i >= NPG - k);
        int node = g * NPG + idx;
        if (nm_out) nm_out[node] = keep ? 1.f : 0.f;
        unsigned ou = (kh & 0x80000000u) ? (kh & 0x7FFFFFFFu) : ~kh;
        if (keep) {
            g_ts1[node] = tanhf(__uint_as_float(ou));
            g_L1[g * k + (i - (NPG - k))] = node;
        } else if (mode == 1) {
            g_ts1[node] = 0.f;
        }
    }
}

// bufC[alive rows] = bufB * ts1 (only alive rows are ever read downstream)
__global__ void k_hupdate_alive(const float* __restrict__ hin,
                                float* __restrict__ hout) {
    int w    = (blockIdx.x * blockDim.x + threadIdx.x) >> 5;
    int lane = threadIdx.x & 31;
    if (w >= NALIVE1) return;
    int n = g_L1[w];
    float tsv = g_ts1[n];
    float4 v = *(const float4*)(hin + (size_t)n * HID + lane * 4);
    v.x *= tsv; v.y *= tsv; v.z *= tsv; v.w *= tsv;
    *(float4*)(hout + (size_t)n * HID + lane * 4) = v;
}

// ---------------- readout: gather only the 512 survivors per graph ------------
__global__ void k_graph_reduce(const float* __restrict__ h) {
    __shared__ float ts[128];
    __shared__ int   nd[128];
    int g = blockIdx.x >> 2, chunk = blockIdx.x & 3;
    int c = threadIdx.x;
    int slot = g * 512 + chunk * 128 + c;
    int node = g_L1[slot];
    nd[c] = node;
    ts[c] = g_ts1[node];
    __syncthreads();
    float s = 0.f;
    #pragma unroll 8
    for (int n = 0; n < 128; n++)
        s += h[(size_t)nd[n] * HID + c] * ts[n];
    atomicAdd(&g_gvec[g * HID + c], s * (1.f / 512.f));
}

__global__ __launch_bounds__(1024) void k_head(
    const float* __restrict__ W5, const float* __restrict__ b5,
    const float* __restrict__ W6, const float* __restrict__ b6,
    float* __restrict__ out)
{
    __shared__ float hid[NG][64];
    int w = threadIdx.x >> 5, lane = threadIdx.x & 31;
    for (int c = lane; c < 64; c += 32) {
        float s = b5[c];
        #pragma unroll 8
        for (int i = 0; i < HID; i++) s += g_gvec[w * HID + i] * W5[i * 64 + c];
        hid[w][c] = fmaxf(s, 0.f);
    }
    __syncwarp();
    if (lane == 0) {
        float l0 = b6[0], l1 = b6[1];
        #pragma unroll 8
        for (int i = 0; i < 64; i++) {
            float hv = hid[w][i];
            l0 += hv * W6[i * 2 + 0];
            l1 += hv * W6[i * 2 + 1];
        }
        float m = fmaxf(l0, l1);
        float lse = m + logf(expf(l0 - m) + expf(l1 - m));
        out[w * 2 + 0] = l0 - lse;
        out[w * 2 + 1] = l1 - lse;
    }
}

// ---------------- launch ---------------------------------------------------------
extern "C" void kernel_launch(void* const* d_in, const int* in_sizes, int n_in,
                              void* d_out, int out_size) {
    (void)in_sizes; (void)n_in; (void)out_size;
    const float* x   = (const float*)d_in[0];
    const int*   ei  = (const int*)d_in[1];
    const int*   src = ei;
    const int*   dst = ei + NE;
    const float* Wl1 = (const float*)d_in[4],  *bl1 = (const float*)d_in[5],  *Wr1 = (const float*)d_in[6];
    const float* Wl2 = (const float*)d_in[7],  *bl2 = (const float*)d_in[8],  *Wr2 = (const float*)d_in[9];
    const float* Wl3 = (const float*)d_in[10], *bl3 = (const float*)d_in[11], *Wr3 = (const float*)d_in[12];
    const float* Wl4 = (const float*)d_in[13], *bl4 = (const float*)d_in[14], *Wr4 = (const float*)d_in[15];
    const float* Prel1 = (const float*)d_in[16], *prb1 = (const float*)d_in[17], *Proot1 = (const float*)d_in[18];
    const float* Prel2 = (const float*)d_in[19], *prb2 = (const float*)d_in[20], *Proot2 = (const float*)d_in[21];
    const float* W5 = (const float*)d_in[22], *b5 = (const float*)d_in[23];
    const float* W6 = (const float*)d_in[24], *b6 = (const float*)d_in[25];
    float* out = (float*)d_out;

    float *bufA, *bufB, *bufC, *agg, *nm1, *ts1;
    int *L1;
    cudaGetSymbolAddress((void**)&bufA, g_bufA);
    cudaGetSymbolAddress((void**)&bufB, g_bufB);
    cudaGetSymbolAddress((void**)&bufC, g_bufC);
    cudaGetSymbolAddress((void**)&agg,  g_agg);
    cudaGetSymbolAddress((void**)&nm1,  g_nm1);
    cudaGetSymbolAddress((void**)&ts1,  g_ts1);
    cudaGetSymbolAddress((void**)&L1,   g_L1);

    const int SMEM = 98304;   // 3 stages x (16KB A + 16KB B)
    cudaFuncSetAttribute(k_gemm<false,false>,
                         cudaFuncAttributeMaxDynamicSharedMemorySize, SMEM);
    cudaFuncSetAttribute(k_gemm<false,true>,
                         cudaFuncAttributeMaxDynamicSharedMemorySize, SMEM);
    cudaFuncSetAttribute(k_gemm<true,false>,
                         cudaFuncAttributeMaxDynamicSharedMemorySize, SMEM);
    cudaFuncSetAttribute(k_gemm<true,true>,
                         cudaFuncAttributeMaxDynamicSharedMemorySize, SMEM);

    const int AGG_FULL    = (NT * 32) / 256;
    const int AGG_COMPACT = (NALIVE1 * 32) / 256;
    const int GEMM_FULL    = NT / 128;       // 512 blocks
    const int GEMM_COMPACT = NALIVE1 / 128;  // 256 blocks

    // 1-3: CSR build (g_cnt/g_cursor zero at entry; restored by k_score_agg)
    k_hist<<<NE / 256, 256>>>(dst);
    k_scan<<<1, 1024>>>();
    k_scatter<<<NE / 256, 256>>>(src, dst);

    // 4: agg(x)
    k_agg<<<AGG_FULL, 256>>>(x, agg, nullptr, nullptr, nullptr, NT);
    // 5: SAGE 1: bufA = relu(agg@Wl1 + x@Wr1 + bl1)
    k_gemm<false,false><<<GEMM_FULL, 256, SMEM>>>(
        agg, Wl1, x, Wr1, bl1, nullptr, nullptr, nullptr, nullptr, bufA);
    // 6-7: SAGE 2 (+ pool-1 score GEMVs in epilogue)
    k_agg<<<AGG_FULL, 256>>>(bufA, agg, nullptr, nullptr, nullptr, NT);
    k_gemm<false,true><<<GEMM_FULL, 256, SMEM>>>(
        agg, Wl2, bufA, Wr2, bl2, nullptr, Prel1, Proot1, prb1, bufB);

    // 8-9: SAGPool 1 (k=1024): score scatter, sort -> nm1 + ts1 + alive list L1
    k_score_agg<<<NT / 256, 256>>>(nullptr);
    k_topk<<<NG, 1024>>>(nm1, 1024, 1);
    // 10: bufC[alive] = bufB * ts1
    k_hupdate_alive<<<AGG_COMPACT, 256>>>(bufB, bufC);

    // 11-12: SAGE 3 on compacted rows (agg reads bufB with feature weight ts1)
    k_agg<<<AGG_COMPACT, 256>>>(bufB, agg, ts1, nm1, L1, NALIVE1);
    k_gemm<true,false><<<GEMM_COMPACT, 256, SMEM>>>(
        agg, Wl3, bufC, Wr3, bl3, L1, nullptr, nullptr, nullptr, bufA);
    // 13-14: SAGE 4 (+ pool-2 score GEMVs in epilogue, alive rows only)
    k_agg<<<AGG_COMPACT, 256>>>(bufA, agg, nm1, nm1, L1, NALIVE1);
    k_gemm<true,true><<<GEMM_COMPACT, 256, SMEM>>>(
        agg, Wl4, bufA, Wr4, bl4, L1, Prel2, Proot2, prb2, bufB);

    // 15-16: SAGPool 2 (k=512): emits ts1 + alive list (stride 512), zeroes gvec
    k_score_agg<<<NT / 256, 256>>>(nm1);
    k_topk<<<NG, 1024>>>(nullptr, 512, 2);

    // 17-18: readout over survivors only
    k_graph_reduce<<<128, 128>>>(bufB);
    k_head<<<1, 1024>>>(W5, b5, W6, b6, out);
}

// round 17
// speedup vs baseline: 1.0269x; 1.0101x over previous
#include <cuda_runtime.h>
#include <math.h>
#include <stdint.h>

#define NT   65536
#define NG   32
#define NPG  2048
#define NE   524288
#define HID  128
#define NALIVE1 32768

typedef unsigned long long ull;

// ---------------- scratch (device globals; zero-initialized at load) ---------
__device__ float g_bufA[(size_t)NT * HID];
__device__ float g_bufB[(size_t)NT * HID];
__device__ float g_agg [(size_t)NT * HID];
__device__ int   g_cnt[NT];
__device__ int   g_cursor[NT];
__device__ int   g_rowptr[NT + 1];
__device__ int   g_col[NE];
__device__ float g_prel[NT];
__device__ float g_base[NT];
__device__ float g_score[NT];
__device__ float g_nm1[NT];
__device__ float g_ts1[NT];
__device__ float g_gvec[NG * HID];
__device__ int   g_L1[NALIVE1];

// ---------------- helpers ------------------------------------------------------
__device__ __forceinline__ ull ffma2(ull a, ull b, ull c) {
    ull d;
    asm("fma.rn.f32x2 %0, %1, %2, %3;" : "=l"(d) : "l"(a), "l"(b), "l"(c));
    return d;
}
__device__ __forceinline__ ull fmul2(ull a, ull b) {
    ull d;
    asm("mul.rn.f32x2 %0, %1, %2;" : "=l"(d) : "l"(a), "l"(b));
    return d;
}
__device__ __forceinline__ ull dup2(float x) {
    ull r;
    asm("mov.b64 %0, {%1, %1};" : "=l"(r) : "f"(x));
    return r;
}
__device__ __forceinline__ ull dup_lo(ull v) {
    ull r;
    asm("{\n\t.reg .b32 l, h;\n\tmov.b64 {l, h}, %1;\n\tmov.b64 %0, {l, l};\n\t}"
        : "=l"(r) : "l"(v));
    return r;
}
__device__ __forceinline__ ull dup_hi(ull v) {
    ull r;
    asm("{\n\t.reg .b32 l, h;\n\tmov.b64 {l, h}, %1;\n\tmov.b64 %0, {h, h};\n\t}"
        : "=l"(r) : "l"(v));
    return r;
}
__device__ __forceinline__ void unpack2(ull v, float& lo, float& hi) {
    asm("mov.b64 {%0, %1}, %2;" : "=f"(lo), "=f"(hi) : "l"(v));
}
__device__ __forceinline__ uint32_t s2u(const void* p) {
    return (uint32_t)__cvta_generic_to_shared(p);
}
__device__ __forceinline__ void cp16(uint32_t saddr, const void* gaddr) {
    asm volatile("cp.async.cg.shared.global [%0], [%1], 16;"
                 :: "r"(saddr), "l"(gaddr));
}
__device__ __forceinline__ void cp_commit() {
    asm volatile("cp.async.commit_group;" ::: "memory");
}
template<int N> __device__ __forceinline__ void cp_wait() {
    asm volatile("cp.async.wait_group %0;" :: "n"(N) : "memory");
}

// ---------------- CSR build ----------------------------------------------------
__global__ void k_hist(const int* __restrict__ dst) {
    int e = blockIdx.x * blockDim.x + threadIdx.x;
    if (e < NE) atomicAdd(&g_cnt[dst[e]], 1);   // restored to 0 by k_score_agg
}

__global__ void k_scan() {
    __shared__ int sums[1024];
    int t = threadIdx.x;
    int base = t * 64;
    int s = 0;
    #pragma unroll 8
    for (int i = 0; i < 64; i++) s += g_cnt[base + i];
    sums[t] = s;
    __syncthreads();
    for (int off = 1; off < 1024; off <<= 1) {
        int v = (t >= off) ? sums[t - off] : 0;
        __syncthreads();
        sums[t] += v;
        __syncthreads();
    }
    int run = (t == 0) ? 0 : sums[t - 1];
    for (int i = 0; i < 64; i++) { g_rowptr[base + i] = run; run += g_cnt[base + i]; }
    if (t == 1023) g_rowptr[NT] = run;
}

__global__ void k_scatter(const int* __restrict__ src, const int* __restrict__ dst) {
    int e = blockIdx.x * blockDim.x + threadIdx.x;
    if (e >= NE) return;
    int d = dst[e];
    int pos = g_rowptr[d] + atomicAdd(&g_cursor[d], 1);  // restored later
    g_col[pos] = src[e];
}

// ---------------- GEMM: 128x128 tile, 3-stage cp.async pipeline, f32x2 --------
// acc = A1@W1 (phases 0-3) [ *= mscale[row] if MID ] + A2@W2 (phases 4-7);
// out = relu(acc + bias).
// G1/G2: Lmap-gather rows of A1/A2 in staging. IDXO: Lmap-scatter output rows.
// SCORES: emit g_prel/g_base pool score GEMVs from post-relu rows.
__device__ __forceinline__ void stage_phase(
    const float* __restrict__ Ap, const float* __restrict__ Wp, int kk,
    const int* __restrict__ Lmap, int r0, bool gather,
    float* Asb, float* Bsb, int tid)
{
    #pragma unroll
    for (int i = 0; i < 4; i++) {
        int c = tid + i * 256;          // 128 rows x 8 16B-chunks
        int row = c >> 3, q = c & 7;
        int grow = gather ? __ldg(&Lmap[r0 + row]) : (r0 + row);
        cp16(s2u(Asb + row * 32 + q * 4),
             Ap + (size_t)grow * 128 + kk + q * 4);
    }
    #pragma unroll
    for (int i = 0; i < 4; i++) {
        int c = tid + i * 256;          // 32 k x 32 16B-chunks
        int k = c >> 5, q = c & 31;
        cp16(s2u(Bsb + k * 128 + q * 4),
             Wp + (size_t)(kk + k) * 128 + q * 4);
    }
}

template<bool G1, bool G2, bool IDXO, bool MID, bool SCORES>
__global__ __launch_bounds__(256, 2) void k_gemm(
    const float* __restrict__ A1, const float* __restrict__ W1,
    const float* __restrict__ A2, const float* __restrict__ W2,
    const float* __restrict__ bias, const int* __restrict__ Lmap,
    const float* __restrict__ Prel, const float* __restrict__ Proot,
    const float* __restrict__ prb, const float* __restrict__ mscale,
    float* __restrict__ out)
{
    extern __shared__ float sm[];
    float* As = sm;               // 3 x 128 x 32
    float* Bs = sm + 12288;       // 3 x 32 x 128
    const int NPH = 8;
    int tid = threadIdx.x;
    int r0 = blockIdx.x * 128;
    int ty = tid >> 4, tx = tid & 15;   // rows ty*8+i, col-pairs tx+16j

    ull acc[8][4];
    #pragma unroll
    for (int i = 0; i < 8; i++)
        #pragma unroll
        for (int j = 0; j < 4; j++) acc[i][j] = 0ULL;

    // prologue: stage phases 0 and 1
    stage_phase(A1, W1, 0, Lmap, r0, G1, As, Bs, tid);
    cp_commit();
    stage_phase(A1, W1, 32, Lmap, r0, G1, As + 4096, Bs + 4096, tid);
    cp_commit();

    for (int p = 0; p < NPH; p++) {
        int buf = p % 3;
        // prefetch phase p+2 into buffer (p+2)%3 (last read at phase p-1)
        if (p + 2 < NPH) {
            int pn = p + 2;
            bool second = (pn >= 4);
            const float* Ap = second ? A2 : A1;
            const float* Wp = second ? W2 : W1;
            bool g = second ? G2 : G1;
            int bn = pn % 3;
            stage_phase(Ap, Wp, (pn & 3) * 32, Lmap, r0, g,
                        As + bn * 4096, Bs + bn * 4096, tid);
            cp_commit();
            cp_wait<2>();           // phase p's group complete
        } else if (p + 1 < NPH) {
            cp_wait<1>();
        } else {
            cp_wait<0>();
        }
        __syncthreads();            // all threads' copies for phase p visible

        const float* Ab = As + buf * 4096 + (ty * 8) * 32;
        const float* Bb = Bs + buf * 4096;
        #pragma unroll 2
        for (int k2 = 0; k2 < 16; k2++) {
            ull ap[8];
            #pragma unroll
            for (int i = 0; i < 8; i++)
                ap[i] = *(const ull*)(Ab + i * 32 + 2 * k2);
            #pragma unroll
            for (int h = 0; h < 2; h++) {
                ull a[8];
                #pragma unroll
                for (int i = 0; i < 8; i++)
                    a[i] = h ? dup_hi(ap[i]) : dup_lo(ap[i]);
                const float* Bk = Bb + (2 * k2 + h) * 128;
                #pragma unroll
                for (int j = 0; j < 4; j++) {
                    ull b = *(const ull*)(Bk + 2 * (tx + 16 * j));
                    #pragma unroll
                    for (int i = 0; i < 8; i++)
                        acc[i][j] = ffma2(a[i], b, acc[i][j]);
                }
            }
        }
        // MID: after the A1@W1 half completes, scale acc rows by mscale
        // (pool-1 ts1): final = ts1*(A1@W1) + A2@W2.
        if (MID && p == 3) {
            #pragma unroll
            for (int i = 0; i < 8; i++) {
                int rl = ty * 8 + i;
                int gr = IDXO ? __ldg(&Lmap[r0 + rl]) : (r0 + rl);
                ull t = dup2(__ldg(&mscale[gr]));
                #pragma unroll
                for (int j = 0; j < 4; j++)
                    acc[i][j] = fmul2(acc[i][j], t);
            }
        }
        __syncthreads();            // done reading buf before it is restaged
    }

    // epilogue: bias + relu (+ scatter) (+ pool score GEMVs)
    float prb0 = SCORES ? __ldg(&prb[0]) : 0.f;
    #pragma unroll
    for (int i = 0; i < 8; i++) {
        int rl = ty * 8 + i;
        int gr = IDXO ? __ldg(&Lmap[r0 + rl]) : (r0 + rl);
        float s1 = 0.f, s2 = 0.f;
        #pragma unroll
        for (int j = 0; j < 4; j++) {
            int cc = 2 * (tx + 16 * j);
            float lo, hi;
            unpack2(acc[i][j], lo, hi);
            lo = fmaxf(lo + bias[cc], 0.f);
            hi = fmaxf(hi + bias[cc + 1], 0.f);
            if (SCORES) {
                s1 += lo * __ldg(&Prel[cc])  + hi * __ldg(&Prel[cc + 1]);
                s2 += lo * __ldg(&Proot[cc]) + hi * __ldg(&Proot[cc + 1]);
            }
            *(float2*)(out + (size_t)gr * 128 + cc) = make_float2(lo, hi);
        }
        if (SCORES) {
            #pragma unroll
            for (int off = 8; off > 0; off >>= 1) {
                s1 += __shfl_xor_sync(0xffffffffu, s1, off, 16);
                s2 += __shfl_xor_sync(0xffffffffu, s2, off, 16);
            }
            if ((tid & 15) == 0) {
                g_prel[gr] = s1;
                g_base[gr] = s2 + prb0;
            }
        }
    }
}

// ---------------- mean aggregation (warp per work item, 8-way MLP) ------------
__global__ void k_agg(const float* __restrict__ h, float* __restrict__ out,
                      const float* __restrict__ wts, const float* __restrict__ nm,
                      const int* __restrict__ L, int nwork) {
    int w    = (blockIdx.x * blockDim.x + threadIdx.x) >> 5;
    int lane = threadIdx.x & 31;
    if (w >= nwork) return;
    int n = L ? __ldg(&L[w]) : w;
    int r0 = g_rowptr[n], r1 = g_rowptr[n + 1];
    float4 acc = make_float4(0.f, 0.f, 0.f, 0.f);
    float cnt = 0.f;
    int j = r0;
    for (; j + 8 <= r1; j += 8) {
        int cI[8];
        #pragma unroll
        for (int q = 0; q < 8; q++) cI[q] = g_col[j + q];
        float wv[8];
        #pragma unroll
        for (int q = 0; q < 8; q++) wv[q] = wts ? wts[cI[q]] : 1.f;
        float4 v[8];
        #pragma unroll
        for (int q = 0; q < 8; q++)
            v[q] = *(const float4*)(h + (size_t)cI[q] * HID + lane * 4);
        #pragma unroll
        for (int q = 0; q < 8; q++) {
            acc.x += v[q].x * wv[q];
            acc.y += v[q].y * wv[q];
            acc.z += v[q].z * wv[q];
            acc.w += v[q].w * wv[q];
        }
        if (nm) {
            #pragma unroll
            for (int q = 0; q < 8; q++) cnt += nm[cI[q]];
        }
    }
    for (; j < r1; j++) {
        int c = g_col[j];
        float ww = wts ? wts[c] : 1.f;
        float4 v = *(const float4*)(h + (size_t)c * HID + lane * 4);
        acc.x += v.x*ww; acc.y += v.y*ww; acc.z += v.z*ww; acc.w += v.w*ww;
        if (nm) cnt += nm[c];
    }
    float inv = nm ? (1.f / fmaxf(cnt, 1.f))
                   : (1.f / fmaxf((float)(r1 - r0), 1.f));
    acc.x *= inv; acc.y *= inv; acc.z *= inv; acc.w *= inv;
    *(float4*)(out + (size_t)w * HID + lane * 4) = acc;
}

// ---------------- pooling ------------------------------------------------------
// score[n] = base[n] + sum_in prel[src]*nm[src]; also restores CSR scratch.
__global__ void k_score_agg(const float* __restrict__ nm) {
    int n = blockIdx.x * blockDim.x + threadIdx.x;
    if (n >= NT) return;
    g_cnt[n] = 0; g_cursor[n] = 0;     // restore for next replay (idempotent)
    if (nm && nm[n] == 0.f) { g_score[n] = -1e30f; return; }
    float s = g_base[n];
    int r0 = g_rowptr[n], r1 = g_rowptr[n + 1];
    int j = r0;
    for (; j + 4 <= r1; j += 4) {
        int c0 = g_col[j], c1 = g_col[j+1], c2 = g_col[j+2], c3 = g_col[j+3];
        float p0 = g_prel[c0] * (nm ? nm[c0] : 1.f);
        float p1 = g_prel[c1] * (nm ? nm[c1] : 1.f);
        float p2 = g_prel[c2] * (nm ? nm[c2] : 1.f);
        float p3 = g_prel[c3] * (nm ? nm[c3] : 1.f);
        s += p0 + p1 + p2 + p3;
    }
    for (; j < r1; j++) {
        int c = g_col[j];
        s += g_prel[c] * (nm ? nm[c] : 1.f);
    }
    g_score[n] = s;
}

// exact top-k per graph via bitonic sort.
// mode 1 (pool-1, k=1024): writes full 0/1 mask to nm_out, ts1 = tanh(score)
//   for kept / 0 for dead, alive list at g_L1[g*k ..].
// mode 2 (pool-2, k=512): nm_out unused (nullptr); ts1 + alive list for kept
//   only; zeroes g_gvec.
__global__ __launch_bounds__(1024) void k_topk(float* __restrict__ nm_out,
                                               int k, int mode) {
    __shared__ ull keys[NPG];
    int g = blockIdx.x, t = threadIdx.x;
    if (mode == 2 && t < 128) g_gvec[g * 128 + t] = 0.f;
    for (int i = t; i < NPG; i += 1024) {
        float f = g_score[g * NPG + i];
        unsigned u = __float_as_uint(f);
        u = (u & 0x80000000u) ? ~u : (u | 0x80000000u);   // order-preserving map
        keys[i] = (((ull)u) << 32) | (unsigned)(0xFFFFFFFFu - i);
    }
    __syncthreads();
    for (int ksz = 2; ksz <= NPG; ksz <<= 1) {
        for (int j = ksz >> 1; j > 0; j >>= 1) {
            int i   = ((t & ~(j - 1)) << 1) | (t & (j - 1));
            int ixj = i | j;
            bool asc = ((i & ksz) == 0);
            ull a = keys[i], b = keys[ixj];
            if ((a > b) == asc) { keys[i] = b; keys[ixj] = a; }
            __syncthreads();
        }
    }
    for (int i = t; i < NPG; i += 1024) {
        ull key = keys[i];
        unsigned kh = (unsigned)(key >> 32);
        int idx = (int)(0xFFFFFFFFu - (unsigned)(key & 0xFFFFFFFFu));
        bool keep = (i >= NPG - k);
        int node = g * NPG + idx;
        if (nm_out) nm_out[node] = keep ? 1.f : 0.f;
        unsigned ou = (kh & 0x80000000u) ? (kh & 0x7FFFFFFFu) : ~kh;
        if (keep) {
            g_ts1[node] = tanhf(__uint_as_float(ou));
            g_L1[g * k + (i - (NPG - k))] = node;
        } else if (mode == 1) {
            g_ts1[node] = 0.f;
        }
    }
}

// ---------------- readout: gather only the 512 survivors per graph ------------
__global__ void k_graph_reduce(const float* __restrict__ h) {
    __shared__ float ts[128];
    __shared__ int   nd[128];
    int g = blockIdx.x >> 2, chunk = blockIdx.x & 3;
    int c = threadIdx.x;
    int slot = g * 512 + chunk * 128 + c;
    int node = g_L1[slot];
    nd[c] = node;
    ts[c] = g_ts1[node];
    __syncthreads();
    float s = 0.f;
    #pragma unroll 8
    for (int n = 0; n < 128; n++)
        s += h[(size_t)nd[n] * HID + c] * ts[n];
    atomicAdd(&g_gvec[g * HID + c], s * (1.f / 512.f));
}

__global__ __launch_bounds__(1024) void k_head(
    const float* __restrict__ W5, const float* __restrict__ b5,
    const float* __restrict__ W6, const float* __restrict__ b6,
    float* __restrict__ out)
{
    __shared__ float hid[NG][64];
    int w = threadIdx.x >> 5, lane = threadIdx.x & 31;
    for (int c = lane; c < 64; c += 32) {
        float s = b5[c];
        #pragma unroll 8
        for (int i = 0; i < HID; i++) s += g_gvec[w * HID + i] * W5[i * 64 + c];
        hid[w][c] = fmaxf(s, 0.f);
    }
    __syncwarp();
    if (lane == 0) {
        float l0 = b6[0], l1 = b6[1];
        #pragma unroll 8
        for (int i = 0; i < 64; i++) {
            float hv = hid[w][i];
            l0 += hv * W6[i * 2 + 0];
            l1 += hv * W6[i * 2 + 1];
        }
        float m = fmaxf(l0, l1);
        float lse = m + logf(expf(l0 - m) + expf(l1 - m));
        out[w * 2 + 0] = l0 - lse;
        out[w * 2 + 1] = l1 - lse;
    }
}

// ---------------- launch ---------------------------------------------------------
extern "C" void kernel_launch(void* const* d_in, const int* in_sizes, int n_in,
                              void* d_out, int out_size) {
    (void)in_sizes; (void)n_in; (void)out_size;
    const float* x   = (const float*)d_in[0];
    const int*   ei  = (const int*)d_in[1];
    const int*   src = ei;
    const int*   dst = ei + NE;
    const float* Wl1 = (const float*)d_in[4],  *bl1 = (const float*)d_in[5],  *Wr1 = (const float*)d_in[6];
    const float* Wl2 = (const float*)d_in[7],  *bl2 = (const float*)d_in[8],  *Wr2 = (const float*)d_in[9];
    const float* Wl3 = (const float*)d_in[10], *bl3 = (const float*)d_in[11], *Wr3 = (const float*)d_in[12];
    const float* Wl4 = (const float*)d_in[13], *bl4 = (const float*)d_in[14], *Wr4 = (const float*)d_in[15];
    const float* Prel1 = (const float*)d_in[16], *prb1 = (const float*)d_in[17], *Proot1 = (const float*)d_in[18];
    const float* Prel2 = (const float*)d_in[19], *prb2 = (const float*)d_in[20], *Proot2 = (const float*)d_in[21];
    const float* W5 = (const float*)d_in[22], *b5 = (const float*)d_in[23];
    const float* W6 = (const float*)d_in[24], *b6 = (const float*)d_in[25];
    float* out = (float*)d_out;

    float *bufA, *bufB, *agg, *nm1, *ts1;
    int *L1;
    cudaGetSymbolAddress((void**)&bufA, g_bufA);
    cudaGetSymbolAddress((void**)&bufB, g_bufB);
    cudaGetSymbolAddress((void**)&agg,  g_agg);
    cudaGetSymbolAddress((void**)&nm1,  g_nm1);
    cudaGetSymbolAddress((void**)&ts1,  g_ts1);
    cudaGetSymbolAddress((void**)&L1,   g_L1);

    const int SMEM = 98304;   // 3 stages x (16KB A + 16KB B)
    cudaFuncSetAttribute(k_gemm<false,false,false,false,false>,
                         cudaFuncAttributeMaxDynamicSharedMemorySize, SMEM);
    cudaFuncSetAttribute(k_gemm<false,false,false,false,true>,
                         cudaFuncAttributeMaxDynamicSharedMemorySize, SMEM);
    cudaFuncSetAttribute(k_gemm<true,false,true,true,false>,
                         cudaFuncAttributeMaxDynamicSharedMemorySize, SMEM);
    cudaFuncSetAttribute(k_gemm<false,true,true,false,true>,
                         cudaFuncAttributeMaxDynamicSharedMemorySize, SMEM);

    const int AGG_FULL    = (NT * 32) / 256;
    const int AGG_COMPACT = (NALIVE1 * 32) / 256;
    const int GEMM_FULL    = NT / 128;       // 512 blocks
    const int GEMM_COMPACT = NALIVE1 / 128;  // 256 blocks

    // 1-3: CSR build (g_cnt/g_cursor zero at entry; restored by k_score_agg)
    k_hist<<<NE / 256, 256>>>(dst);
    k_scan<<<1, 1024>>>();
    k_scatter<<<NE / 256, 256>>>(src, dst);

    // 4: agg(x)
    k_agg<<<AGG_FULL, 256>>>(x, agg, nullptr, nullptr, nullptr, NT);
    // 5: SAGE 1: bufA = relu(agg@Wl1 + x@Wr1 + bl1)
    k_gemm<false,false,false,false,false><<<GEMM_FULL, 256, SMEM>>>(
        agg, Wl1, x, Wr1, bl1, nullptr, nullptr, nullptr, nullptr, nullptr, bufA);
    // 6-7: SAGE 2 (+ pool-1 score GEMVs in epilogue)
    k_agg<<<AGG_FULL, 256>>>(bufA, agg, nullptr, nullptr, nullptr, NT);
    k_gemm<false,false,false,false,true><<<GEMM_FULL, 256, SMEM>>>(
        agg, Wl2, bufA, Wr2, bl2, nullptr, Prel1, Proot1, prb1, nullptr, bufB);

    // 8-9: SAGPool 1 (k=1024): score scatter, sort -> nm1 + ts1 + alive list L1
    k_score_agg<<<NT / 256, 256>>>(nullptr);
    k_topk<<<NG, 1024>>>(nm1, 1024, 1);

    // 10-11: SAGE 3 on compacted rows, pool scale fused mid-GEMM:
    //   bufA[alive] = relu( ts1*(bufB@Wr3) + agg@Wl3 + bl3 )
    //   (A1=bufB gathered, scaled after phase 3; A2=agg direct)
    k_agg<<<AGG_COMPACT, 256>>>(bufB, agg, ts1, nm1, L1, NALIVE1);
    k_gemm<true,false,true,true,false><<<GEMM_COMPACT, 256, SMEM>>>(
        bufB, Wr3, agg, Wl3, bl3, L1, nullptr, nullptr, nullptr, ts1, bufA);
    // 12-13: SAGE 4 (+ pool-2 score GEMVs in epilogue, alive rows only)
    k_agg<<<AGG_COMPACT, 256>>>(bufA, agg, nm1, nm1, L1, NALIVE1);
    k_gemm<false,true,true,false,true><<<GEMM_COMPACT, 256, SMEM>>>(
        agg, Wl4, bufA, Wr4, bl4, L1, Prel2, Proot2, prb2, nullptr, bufB);

    // 14-15: SAGPool 2 (k=512): emits ts1 + alive list (stride 512), zeroes gvec
    k_score_agg<<<NT / 256, 256>>>(nm1);
    k_topk<<<NG, 1024>>>(nullptr, 512, 2);

    // 16-17: readout over survivors only
    k_graph_reduce<<<128, 128>>>(bufB);
    k_head<<<1, 1024>>>(W5, b5, W6, b6, out);
}